// round 11
// baseline (speedup 1.0000x reference)
#include <cuda_runtime.h>
#include <cuda_fp16.h>

#define N_CELL 50000
#define N_NET  10000
#define N_GCELL 20000
#define NE 100000
#define D 32
#define DP 16

#define OUT_NET_OFF   (N_CELL*D)            // 1,600,000
#define OUT_GCELL_OFF ((N_CELL+N_NET)*D)    // 1,920,000

// degree counter layout inside g_cnt / g_scale
#define CNT_PINS_SRC   0         // N_CELL   (gc: deg^-1/2)
#define CNT_PINS_DST   50000     // N_NET    (gc)
#define CNT_PINNED_DST 60000     // N_CELL   (nn: 1/deg)
#define CNT_CONN_SRC   110000    // N_GCELL  (gc)
#define CNT_CONN_DST   130000    // N_GCELL  (gc)
#define CNT_PT_SRC     150000    // N_CELL   (gc)
#define CNT_PT_DST     200000    // N_GCELL  (gc)
#define CNT_PF_DST     220000    // N_CELL   (nn: 1/deg)
#define CNT_TOTAL      270000

#define WT_PAD 18                 // [i][o][p] smem layout, o-stride 18 (16 p + 2 pad)
#define WT_SIZE (D * D * WT_PAD)  // 18432 floats

// ---------------- scratch (device globals; no allocation allowed) ----------
// g_cnt is zero-initialized at module load; scale_kernel resets it after use,
// so every kernel_launch invocation starts from zeroed counts.
__device__ int   g_cnt[CNT_TOTAL];
__device__ float g_scale[CNT_TOTAL];      // precomputed per-node normalization
// gc feats now fp16 (halves gather traffic in edge phase)
__device__ __align__(16) __half g_feat_pins[N_CELL*D];   // node @ W_pins (unscaled)
__device__ __align__(16) __half g_feat_pt[N_CELL*D];     // node @ W_pt   (unscaled)
__device__ __align__(16) __half g_feat_conn[N_GCELL*D];  // hanna @ W_connect (unscaled)
// M layout: per node, halves indexed [pp][o][2] : offset = pp*64 + o*2 + (p&1)
__device__ __align__(16) __half g_Mnet_h[N_NET*DP*D];
__device__ float g_cnet[N_NET*D];
__device__ __align__(16) __half g_Mhan_h[N_GCELL*DP*D];
__device__ float g_chan[N_GCELL*D];

__device__ __forceinline__ void red_add_v4(float* p, float4 v) {
    asm volatile("red.global.add.v4.f32 [%0], {%1,%2,%3,%4};"
                 :: "l"(p), "f"(v.x), "f"(v.y), "f"(v.z), "f"(v.w) : "memory");
}
__device__ __forceinline__ unsigned long long pack2(float x, float y) {
    unsigned long long r;
    asm("mov.b64 %0, {%1,%2};" : "=l"(r) : "f"(x), "f"(y));
    return r;
}
__device__ __forceinline__ void unpack2(unsigned long long v, float& x, float& y) {
    asm("mov.b64 {%0,%1}, %2;" : "=f"(x), "=f"(y) : "l"(v));
}
__device__ __forceinline__ unsigned long long fma2(unsigned long long a,
                                                   unsigned long long b,
                                                   unsigned long long c) {
    unsigned long long d;
    asm("fma.rn.f32x2 %0, %1, %2, %3;" : "=l"(d) : "l"(a), "l"(b), "l"(c));
    return d;
}

// =============== fused phase-A kernel: m2 | count | bias | net | node | conn ========
#define MR 4
#define B_M2    938                      // ceil(7500 row-groups / 8 warps)
#define B_C     391                      // ceil(NE/256)
#define B_COUNT (8*B_C)                  // 3128
#define B_BIAS  2188                     // ceil((N_CELL+N_GCELL)*D/4 / 256)
#define B_NET   313                      // ceil(N_NET/32)
#define B_NODE  1563                     // ceil(N_CELL/32)
#define B_CONN  625                      // N_GCELL/32
#define B_PHASEA (B_M2 + B_COUNT + B_BIAS + B_NET + B_NODE + B_CONN)   // 8755

__global__ void phaseA_kernel(const int* __restrict__ pins_src, const int* __restrict__ pins_dst,
                              const int* __restrict__ pinned_dst,
                              const int* __restrict__ conn_src, const int* __restrict__ conn_dst,
                              const int* __restrict__ pt_src, const int* __restrict__ pt_dst,
                              const int* __restrict__ pf_dst,
                              const float* __restrict__ node_feat, const float* __restrict__ net_feat,
                              const float* __restrict__ hanna_feat,
                              const float* __restrict__ W_net, const float* __restrict__ b_net,
                              const float* __restrict__ W_topo, const float* __restrict__ b_topo,
                              const float* __restrict__ W_pins, const float* __restrict__ b_pins,
                              const float* __restrict__ W_connect, const float* __restrict__ b_connect,
                              const float* __restrict__ W_pt, const float* __restrict__ b_pt,
                              const float* __restrict__ b_pinned, const float* __restrict__ b_pf,
                              float* __restrict__ out) {
    __shared__ float sA[D*D], sB[D*D];
    __shared__ float sH[8*4*32];
    extern __shared__ float s[];   // 80KB, used only by the m2 region
    int b = blockIdx.x;
    int wid = threadIdx.x >> 5, lane = threadIdx.x & 31;

    if (b < B_M2) {
        // ================= m2 region: per-node NNConv matrices ==================
        float* sW2 = s;                 // WT_SIZE = 18432 floats
        float* sb  = s + WT_SIZE;       // 1024
        float* sHm = s + WT_SIZE + D*D; // 8 warps * MR * 32 = 1024
        for (int t = threadIdx.x; t < DP*D*D; t += 256) {
            int p = t >> 10;
            int rem = t & 1023;
            int i = rem >> 5;
            int o = rem & 31;
            sW2[i*(D*WT_PAD) + o*WT_PAD + p] = W_topo[t];
        }
        for (int i = threadIdx.x; i < D*D; i += 256) sb[i] = b_topo[i];
        __syncthreads();

        int g = b * 8 + wid;
        const int NGROUPS = (N_NET + N_GCELL) / MR;  // 7500
        if (g >= NGROUPS) return;
        int r0 = g * MR;
        int hbase = wid * (MR*32);

        unsigned int* Mout[MR];
        float* cout[MR];
#pragma unroll
        for (int r = 0; r < MR; r++) {
            int row = r0 + r;
            float hv;
            if (row < N_NET) {
                hv = net_feat[row*D + lane];
                Mout[r] = reinterpret_cast<unsigned int*>(g_Mnet_h + (size_t)row * (DP*D));
                cout[r] = g_cnet + (size_t)row * D;
            } else {
                int rr = row - N_NET;
                hv = hanna_feat[rr*D + lane];
                Mout[r] = reinterpret_cast<unsigned int*>(g_Mhan_h + (size_t)rr * (DP*D));
                cout[r] = g_chan + (size_t)rr * D;
            }
            sHm[hbase + r*32 + lane] = hv;
        }
        __syncwarp();

        unsigned long long acc[MR][DP/2];
        float cacc[MR];
#pragma unroll
        for (int r = 0; r < MR; r++) {
            cacc[r] = 0.f;
#pragma unroll
            for (int pp = 0; pp < DP/2; pp++) acc[r][pp] = 0ull;
        }

#pragma unroll
        for (int i = 0; i < D; i++) {
            unsigned long long hp[MR];
            float bv = sb[i*D + lane];
#pragma unroll
            for (int r = 0; r < MR; r++) {
                float hv = sHm[hbase + r*32 + i];
                hp[r] = pack2(hv, hv);
                cacc[r] += hv * bv;
            }
            const unsigned long long* wrow =
                reinterpret_cast<const unsigned long long*>(sW2 + i*(D*WT_PAD) + lane*WT_PAD);
#pragma unroll
            for (int pp = 0; pp < DP/2; pp++) {
                unsigned long long wv = wrow[pp];
#pragma unroll
                for (int r = 0; r < MR; r++) acc[r][pp] = fma2(hp[r], wv, acc[r][pp]);
            }
        }

#pragma unroll
        for (int r = 0; r < MR; r++) {
#pragma unroll
            for (int pp = 0; pp < DP/2; pp++) {
                float x, y;
                unpack2(acc[r][pp], x, y);
                __half2 h2 = __floats2half2_rn(x, y);
                Mout[r][pp*32 + lane] = *reinterpret_cast<unsigned int*>(&h2);
            }
            cout[r][lane] = cacc[r];
        }
        return;
    }
    b -= B_M2;

    if (b < B_COUNT) {
        // ================= degree counting (1 graph-direction per region) =======
        int graph = b / B_C;
        int e = (b - graph * B_C) * 256 + threadIdx.x;
        if (e >= NE) return;
        const int* idx;
        int off;
        switch (graph) {
            case 0: idx = pins_src;   off = CNT_PINS_SRC;   break;
            case 1: idx = pins_dst;   off = CNT_PINS_DST;   break;
            case 2: idx = pinned_dst; off = CNT_PINNED_DST; break;
            case 3: idx = conn_src;   off = CNT_CONN_SRC;   break;
            case 4: idx = conn_dst;   off = CNT_CONN_DST;   break;
            case 5: idx = pt_src;     off = CNT_PT_SRC;     break;
            case 6: idx = pt_dst;     off = CNT_PT_DST;     break;
            default: idx = pf_dst;    off = CNT_PF_DST;     break;
        }
        atomicAdd(&g_cnt[off + idx[e]], 1);
        return;
    }
    b -= B_COUNT;

    if (b < B_BIAS) {
        // ================= bias init of cell + gcell output regions ============
        int i = b * 256 + threadIdx.x;                    // float4 index
        const int n_cell_v4 = N_CELL * D / 4;             // 400000
        const int n_gcell_v4 = N_GCELL * D / 4;           // 160000
        if (i < n_cell_v4) {
            int o = (i*4) & (D-1);
            float4 v = make_float4(b_pinned[o] + b_pf[o],   b_pinned[o+1] + b_pf[o+1],
                                   b_pinned[o+2] + b_pf[o+2], b_pinned[o+3] + b_pf[o+3]);
            reinterpret_cast<float4*>(out)[i] = v;
        } else if (i < n_cell_v4 + n_gcell_v4) {
            int k = i - n_cell_v4;
            int o = (k*4) & (D-1);
            float4 v = make_float4(b_connect[o] + b_pt[o],   b_connect[o+1] + b_pt[o+1],
                                   b_connect[o+2] + b_pt[o+2], b_connect[o+3] + b_pt[o+3]);
            reinterpret_cast<float4*>(out + OUT_GCELL_OFF)[k] = v;
        }
        return;
    }
    b -= B_BIAS;

    int hbase = wid * 128;

    if (b < B_NET) {
        // ================= out_net = net_feat @ W_net + b_net + b_pins ==========
        for (int i = threadIdx.x; i < D*D; i += 256) sA[i] = W_net[i];
        __syncthreads();
        int r0 = b * 32 + wid * 4;
#pragma unroll
        for (int r = 0; r < 4; r++) {
            int row = r0 + r;
            sH[hbase + r*32 + lane] = (row < N_NET) ? net_feat[row*D + lane] : 0.f;
        }
        __syncwarp();
        float bv = b_net[lane] + b_pins[lane];
        unsigned long long a01 = pack2(bv, bv), a23 = pack2(bv, bv);
#pragma unroll
        for (int i = 0; i < D; i++) {
            float w = sA[i*D + lane];
            unsigned long long wp = pack2(w, w);
            a01 = fma2(pack2(sH[hbase + i], sH[hbase + 32 + i]), wp, a01);
            a23 = fma2(pack2(sH[hbase + 64 + i], sH[hbase + 96 + i]), wp, a23);
        }
        float x0, x1, x2, x3;
        unpack2(a01, x0, x1); unpack2(a23, x2, x3);
        if (r0 + 0 < N_NET) out[OUT_NET_OFF + (r0+0)*D + lane] = x0;
        if (r0 + 1 < N_NET) out[OUT_NET_OFF + (r0+1)*D + lane] = x1;
        if (r0 + 2 < N_NET) out[OUT_NET_OFF + (r0+2)*D + lane] = x2;
        if (r0 + 3 < N_NET) out[OUT_NET_OFF + (r0+3)*D + lane] = x3;
        return;
    }
    b -= B_NET;

    if (b < B_NODE) {
        // ======== node feats: g_feat_pins = node@W_pins, g_feat_pt = node@W_pt (fp16)
        for (int i = threadIdx.x; i < D*D; i += 256) { sA[i] = W_pins[i]; sB[i] = W_pt[i]; }
        __syncthreads();
        int r0 = b * 32 + wid * 4;
#pragma unroll
        for (int r = 0; r < 4; r++) {
            int row = r0 + r;
            sH[hbase + r*32 + lane] = (row < N_CELL) ? node_feat[row*D + lane] : 0.f;
        }
        __syncwarp();
        unsigned long long p01 = 0ull, p23 = 0ull, q01 = 0ull, q23 = 0ull;
#pragma unroll
        for (int i = 0; i < D; i++) {
            unsigned long long h01 = pack2(sH[hbase + i], sH[hbase + 32 + i]);
            unsigned long long h23 = pack2(sH[hbase + 64 + i], sH[hbase + 96 + i]);
            float wa = sA[i*D + lane];
            unsigned long long wap = pack2(wa, wa);
            float wb = sB[i*D + lane];
            unsigned long long wbp = pack2(wb, wb);
            p01 = fma2(h01, wap, p01); p23 = fma2(h23, wap, p23);
            q01 = fma2(h01, wbp, q01); q23 = fma2(h23, wbp, q23);
        }
        float x0, x1, x2, x3, y0, y1, y2, y3;
        unpack2(p01, x0, x1); unpack2(p23, x2, x3);
        unpack2(q01, y0, y1); unpack2(q23, y2, y3);
        if (r0 + 0 < N_CELL) { g_feat_pins[(r0+0)*D + lane] = __float2half_rn(x0);
                               g_feat_pt[(r0+0)*D + lane]   = __float2half_rn(y0); }
        if (r0 + 1 < N_CELL) { g_feat_pins[(r0+1)*D + lane] = __float2half_rn(x1);
                               g_feat_pt[(r0+1)*D + lane]   = __float2half_rn(y1); }
        if (r0 + 2 < N_CELL) { g_feat_pins[(r0+2)*D + lane] = __float2half_rn(x2);
                               g_feat_pt[(r0+2)*D + lane]   = __float2half_rn(y2); }
        if (r0 + 3 < N_CELL) { g_feat_pins[(r0+3)*D + lane] = __float2half_rn(x3);
                               g_feat_pt[(r0+3)*D + lane]   = __float2half_rn(y3); }
        return;
    }
    b -= B_NODE;

    // ================= gcell feats: g_feat_conn = hanna@W_connect (fp16) ========
    for (int i = threadIdx.x; i < D*D; i += 256) sA[i] = W_connect[i];
    __syncthreads();
    int r0 = b * 32 + wid * 4;
#pragma unroll
    for (int r = 0; r < 4; r++) {
        int row = r0 + r;
        sH[hbase + r*32 + lane] = (row < N_GCELL) ? hanna_feat[row*D + lane] : 0.f;
    }
    __syncwarp();
    unsigned long long a01 = 0ull, a23 = 0ull;
#pragma unroll
    for (int i = 0; i < D; i++) {
        float w = sA[i*D + lane];
        unsigned long long wp = pack2(w, w);
        a01 = fma2(pack2(sH[hbase + i], sH[hbase + 32 + i]), wp, a01);
        a23 = fma2(pack2(sH[hbase + 64 + i], sH[hbase + 96 + i]), wp, a23);
    }
    float x0, x1, x2, x3;
    unpack2(a01, x0, x1); unpack2(a23, x2, x3);
    g_feat_conn[(r0+0)*D + lane] = __float2half_rn(x0);
    g_feat_conn[(r0+1)*D + lane] = __float2half_rn(x1);
    g_feat_conn[(r0+2)*D + lane] = __float2half_rn(x2);
    g_feat_conn[(r0+3)*D + lane] = __float2half_rn(x3);
}

// -------------- counts -> scales (then reset counts for next invocation) --------
__global__ void scale_kernel() {
    int i = blockIdx.x * 256 + threadIdx.x;
    if (i >= CNT_TOTAL) return;
    float c = (float)max(g_cnt[i], 1);
    bool is_nn = (i >= CNT_PINNED_DST && i < CNT_CONN_SRC) || (i >= CNT_PF_DST);
    g_scale[i] = is_nn ? __frcp_rn(c) : rsqrtf(c);
    g_cnt[i] = 0;
}

// ------------- fused edge scatter: 5 regions, one edge-graph per thread ---------
// r=0 pins, r=1 connect, r=2 pt (GraphConv, fp16 feats); r=3 pinned, r=4 pf (NNConv)
#define B_EDGE 3125                                     // NE*8/256

__global__ void edge_kernel(const int* __restrict__ pins_src, const int* __restrict__ pins_dst,
                            const int* __restrict__ conn_src, const int* __restrict__ conn_dst,
                            const int* __restrict__ pt_src, const int* __restrict__ pt_dst,
                            const float* __restrict__ pin_feat,
                            const int* __restrict__ pinned_src, const int* __restrict__ pinned_dst,
                            const float* __restrict__ edge_feat,
                            const int* __restrict__ pf_src, const int* __restrict__ pf_dst,
                            float* __restrict__ out) {
    int r = blockIdx.x / B_EDGE;
    int t = (blockIdx.x - r * B_EDGE) * 256 + threadIdx.x;
    int e = t >> 3, j = t & 7;

    if (r < 3) {
        const int* srcA; const int* dstA; const __half* feat;
        int so, do_; float* ob;
        if (r == 0)      { srcA = pins_src; dstA = pins_dst; feat = g_feat_pins;
                           so = CNT_PINS_SRC; do_ = CNT_PINS_DST; ob = out + OUT_NET_OFF; }
        else if (r == 1) { srcA = conn_src; dstA = conn_dst; feat = g_feat_conn;
                           so = CNT_CONN_SRC; do_ = CNT_CONN_DST; ob = out + OUT_GCELL_OFF; }
        else             { srcA = pt_src; dstA = pt_dst; feat = g_feat_pt;
                           so = CNT_PT_SRC; do_ = CNT_PT_DST; ob = out + OUT_GCELL_OFF; }
        int sI = srcA[e], dI = dstA[e];
        float w = g_scale[so + sI] * g_scale[do_ + dI];
        // 4 halves (8B) at o = 4j..4j+3
        float2 raw = *reinterpret_cast<const float2*>(feat + (size_t)sI*D + j*4);
        const __half2* h2 = reinterpret_cast<const __half2*>(&raw);
        float2 f01 = __half22float2(h2[0]);
        float2 f23 = __half22float2(h2[1]);
        float4 v = make_float4(f01.x * w, f01.y * w, f23.x * w, f23.y * w);
        red_add_v4(ob + (size_t)dI*D + j*4, v);
        return;
    }

    // NNConv region (one graph per thread)
    int which = r - 3;
    const float* ef  = which == 0 ? pin_feat   : edge_feat;
    const int*   src = which == 0 ? pinned_src : pf_src;
    const int*   dst = which == 0 ? pinned_dst : pf_dst;
    const __half* M  = which == 0 ? g_Mnet_h   : g_Mhan_h;
    const float* c   = which == 0 ? g_cnet     : g_chan;
    const float* scl = which == 0 ? g_scale + CNT_PINNED_DST : g_scale + CNT_PF_DST;

    int sI = src[e], dI = dst[e];
    float inv = scl[dI];

    const float4* efp = reinterpret_cast<const float4*>(ef + (size_t)e * DP);
    float4 e0 = efp[0], e1 = efp[1], e2 = efp[2], e3 = efp[3];
    float efv[DP] = { e0.x, e0.y, e0.z, e0.w, e1.x, e1.y, e1.z, e1.w,
                      e2.x, e2.y, e2.z, e2.w, e3.x, e3.y, e3.z, e3.w };

    // M halves layout: pp*64 + o*2 + parity. uint4 index for (pp, lane j): pp*8 + j
    const uint4* Mp = reinterpret_cast<const uint4*>(M + (size_t)sI * (DP*D));
    float4 acc = *reinterpret_cast<const float4*>(c + (size_t)sI*D + j*4);
#pragma unroll
    for (int pp = 0; pp < DP/2; pp++) {
        uint4 v = Mp[pp*8 + j];
        float ef0 = efv[2*pp], ef1 = efv[2*pp+1];
        const __half2* h2 = reinterpret_cast<const __half2*>(&v);
        float2 f0 = __half22float2(h2[0]);
        float2 f1 = __half22float2(h2[1]);
        float2 f2 = __half22float2(h2[2]);
        float2 f3 = __half22float2(h2[3]);
        acc.x += ef0*f0.x + ef1*f0.y;
        acc.y += ef0*f1.x + ef1*f1.y;
        acc.z += ef0*f2.x + ef1*f2.y;
        acc.w += ef0*f3.x + ef1*f3.y;
    }
    acc.x *= inv; acc.y *= inv; acc.z *= inv; acc.w *= inv;
    red_add_v4(out + (size_t)dI*D + j*4, acc);
}

// =====================================================================
extern "C" void kernel_launch(void* const* d_in, const int* in_sizes, int n_in,
                              void* d_out, int out_size) {
    const float* node_feat  = (const float*)d_in[0];
    const float* net_feat   = (const float*)d_in[1];
    const float* pin_feat   = (const float*)d_in[2];
    const float* hanna_feat = (const float*)d_in[3];
    const float* edge_feat  = (const float*)d_in[4];
    const int* pins_src     = (const int*)d_in[5];
    const int* pins_dst     = (const int*)d_in[6];
    const int* pinned_src   = (const int*)d_in[7];
    const int* pinned_dst   = (const int*)d_in[8];
    const int* connect_src  = (const int*)d_in[9];
    const int* connect_dst  = (const int*)d_in[10];
    const int* pt_src       = (const int*)d_in[11];
    const int* pt_dst       = (const int*)d_in[12];
    const int* pf_src       = (const int*)d_in[13];
    const int* pf_dst       = (const int*)d_in[14];
    const float* W_net      = (const float*)d_in[15];
    const float* b_net      = (const float*)d_in[16];
    const float* W_topo     = (const float*)d_in[17];
    const float* b_topo     = (const float*)d_in[18];
    const float* W_pins     = (const float*)d_in[19];
    const float* b_pins     = (const float*)d_in[20];
    const float* W_connect  = (const float*)d_in[21];
    const float* b_connect  = (const float*)d_in[22];
    const float* W_pt       = (const float*)d_in[23];
    const float* b_pt       = (const float*)d_in[24];
    const float* b_pinned   = (const float*)d_in[25];
    const float* b_pf       = (const float*)d_in[26];
    (void)in_sizes; (void)n_in; (void)out_size;

    float* out = (float*)d_out;

    static bool s_init = false;
    static size_t a_smem = (size_t)(WT_SIZE + D*D + 8*MR*32) * sizeof(float); // 81920
    if (!s_init) {
        cudaFuncSetAttribute(phaseA_kernel, cudaFuncAttributeMaxDynamicSharedMemorySize,
                             (int)a_smem);
        s_init = true;
    }

    // 1: fused phase A: M matrices + counting + output init + all small GEMMs
    //    (g_cnt arrives zeroed: zero-init at load, reset by scale_kernel each run)
    phaseA_kernel<<<B_PHASEA, 256, a_smem>>>(
        pins_src, pins_dst, pinned_dst, connect_src, connect_dst, pt_src, pt_dst, pf_dst,
        node_feat, net_feat, hanna_feat,
        W_net, b_net, W_topo, b_topo, W_pins, b_pins, W_connect, b_connect,
        W_pt, b_pt, b_pinned, b_pf, out);

    // 2: counts -> scales (+ reset counts)
    scale_kernel<<<(CNT_TOTAL + 255)/256, 256>>>();

    // 3: fused edge scatters: 5 co-resident regions
    edge_kernel<<<5*B_EDGE, 256>>>(pins_src, pins_dst, connect_src, connect_dst,
                                   pt_src, pt_dst, pin_feat, pinned_src, pinned_dst,
                                   edge_feat, pf_src, pf_dst, out);
}

// round 12
// speedup vs baseline: 1.0414x; 1.0414x over previous
#include <cuda_runtime.h>
#include <cuda_fp16.h>

#define N_CELL 50000
#define N_NET  10000
#define N_GCELL 20000
#define NE 100000
#define D 32
#define DP 16

#define OUT_NET_OFF   (N_CELL*D)            // 1,600,000
#define OUT_GCELL_OFF ((N_CELL+N_NET)*D)    // 1,920,000

// degree counter layout inside g_cnt / g_scale
#define CNT_PINS_SRC   0         // N_CELL   (gc: deg^-1/2)
#define CNT_PINS_DST   50000     // N_NET    (gc)
#define CNT_PINNED_DST 60000     // N_CELL   (nn: 1/deg)
#define CNT_CONN_SRC   110000    // N_GCELL  (gc)
#define CNT_CONN_DST   130000    // N_GCELL  (gc)
#define CNT_PT_SRC     150000    // N_CELL   (gc)
#define CNT_PT_DST     200000    // N_GCELL  (gc)
#define CNT_PF_DST     220000    // N_CELL   (nn: 1/deg)
#define CNT_TOTAL      270000

#define WT_PAD 18                 // [i][o][p] smem layout, o-stride 18 (16 p + 2 pad)
#define WT_SIZE (D * D * WT_PAD)  // 18432 floats

// ---------------- scratch (device globals; no allocation allowed) ----------
// g_cnt is zero-initialized at module load; the scale region of m2_kernel
// resets it to zero after use, so every kernel_launch invocation starts clean.
__device__ int   g_cnt[CNT_TOTAL];
__device__ float g_scale[CNT_TOTAL];      // precomputed per-node normalization
// gc feats in fp16 (halves gather traffic in edge phase)
__device__ __align__(16) __half g_feat_pins[N_CELL*D];   // node @ W_pins (unscaled)
__device__ __align__(16) __half g_feat_pt[N_CELL*D];     // node @ W_pt   (unscaled)
__device__ __align__(16) __half g_feat_conn[N_GCELL*D];  // hanna @ W_connect (unscaled)
// M layout: per node, halves indexed [pp][o][2] : offset = pp*64 + o*2 + (p&1)
__device__ __align__(16) __half g_Mnet_h[N_NET*DP*D];
__device__ float g_cnet[N_NET*D];
__device__ __align__(16) __half g_Mhan_h[N_GCELL*DP*D];
__device__ float g_chan[N_GCELL*D];

__device__ __forceinline__ void red_add_v4(float* p, float4 v) {
    asm volatile("red.global.add.v4.f32 [%0], {%1,%2,%3,%4};"
                 :: "l"(p), "f"(v.x), "f"(v.y), "f"(v.z), "f"(v.w) : "memory");
}
__device__ __forceinline__ unsigned long long pack2(float x, float y) {
    unsigned long long r;
    asm("mov.b64 %0, {%1,%2};" : "=l"(r) : "f"(x), "f"(y));
    return r;
}
__device__ __forceinline__ void unpack2(unsigned long long v, float& x, float& y) {
    asm("mov.b64 {%0,%1}, %2;" : "=f"(x), "=f"(y) : "l"(v));
}
__device__ __forceinline__ unsigned long long fma2(unsigned long long a,
                                                   unsigned long long b,
                                                   unsigned long long c) {
    unsigned long long d;
    asm("fma.rn.f32x2 %0, %1, %2, %3;" : "=l"(d) : "l"(a), "l"(b), "l"(c));
    return d;
}

// =============== fused prep: count | bias | net | node | conn ========
#define B_C     391                      // ceil(NE/256)
#define B_COUNT (8*B_C)                  // 3128
#define B_BIAS  2188                     // ceil((N_CELL+N_GCELL)*D/4 / 256)
#define B_NET   313                      // ceil(N_NET/32)
#define B_NODE  1563                     // ceil(N_CELL/32)
#define B_CONN  625                      // N_GCELL/32
#define B_PREP  (B_COUNT + B_BIAS + B_NET + B_NODE + B_CONN)   // 7817

__global__ void __launch_bounds__(256, 6)
prep_kernel(const int* __restrict__ pins_src, const int* __restrict__ pins_dst,
            const int* __restrict__ pinned_dst,
            const int* __restrict__ conn_src, const int* __restrict__ conn_dst,
            const int* __restrict__ pt_src, const int* __restrict__ pt_dst,
            const int* __restrict__ pf_dst,
            const float* __restrict__ node_feat, const float* __restrict__ net_feat,
            const float* __restrict__ hanna_feat,
            const float* __restrict__ W_net, const float* __restrict__ b_net,
            const float* __restrict__ W_pins, const float* __restrict__ b_pins,
            const float* __restrict__ W_connect, const float* __restrict__ b_connect,
            const float* __restrict__ W_pt, const float* __restrict__ b_pt,
            const float* __restrict__ b_pinned, const float* __restrict__ b_pf,
            float* __restrict__ out) {
    __shared__ float sA[D*D], sB[D*D];
    __shared__ float sH[8*4*32];
    int b = blockIdx.x;

    if (b < B_COUNT) {
        int graph = b / B_C;
        int e = (b - graph * B_C) * 256 + threadIdx.x;
        if (e >= NE) return;
        const int* idx;
        int off;
        switch (graph) {
            case 0: idx = pins_src;   off = CNT_PINS_SRC;   break;
            case 1: idx = pins_dst;   off = CNT_PINS_DST;   break;
            case 2: idx = pinned_dst; off = CNT_PINNED_DST; break;
            case 3: idx = conn_src;   off = CNT_CONN_SRC;   break;
            case 4: idx = conn_dst;   off = CNT_CONN_DST;   break;
            case 5: idx = pt_src;     off = CNT_PT_SRC;     break;
            case 6: idx = pt_dst;     off = CNT_PT_DST;     break;
            default: idx = pf_dst;    off = CNT_PF_DST;     break;
        }
        atomicAdd(&g_cnt[off + idx[e]], 1);
        return;
    }
    b -= B_COUNT;

    if (b < B_BIAS) {
        int i = b * 256 + threadIdx.x;                    // float4 index
        const int n_cell_v4 = N_CELL * D / 4;             // 400000
        const int n_gcell_v4 = N_GCELL * D / 4;           // 160000
        if (i < n_cell_v4) {
            int o = (i*4) & (D-1);
            float4 v = make_float4(b_pinned[o] + b_pf[o],   b_pinned[o+1] + b_pf[o+1],
                                   b_pinned[o+2] + b_pf[o+2], b_pinned[o+3] + b_pf[o+3]);
            reinterpret_cast<float4*>(out)[i] = v;
        } else if (i < n_cell_v4 + n_gcell_v4) {
            int k = i - n_cell_v4;
            int o = (k*4) & (D-1);
            float4 v = make_float4(b_connect[o] + b_pt[o],   b_connect[o+1] + b_pt[o+1],
                                   b_connect[o+2] + b_pt[o+2], b_connect[o+3] + b_pt[o+3]);
            reinterpret_cast<float4*>(out + OUT_GCELL_OFF)[k] = v;
        }
        return;
    }
    b -= B_BIAS;

    int wid = threadIdx.x >> 5, lane = threadIdx.x & 31;
    int hbase = wid * 128;

    if (b < B_NET) {
        for (int i = threadIdx.x; i < D*D; i += 256) sA[i] = W_net[i];
        __syncthreads();
        int r0 = b * 32 + wid * 4;
#pragma unroll
        for (int r = 0; r < 4; r++) {
            int row = r0 + r;
            sH[hbase + r*32 + lane] = (row < N_NET) ? net_feat[row*D + lane] : 0.f;
        }
        __syncwarp();
        float bv = b_net[lane] + b_pins[lane];
        unsigned long long a01 = pack2(bv, bv), a23 = pack2(bv, bv);
#pragma unroll
        for (int i = 0; i < D; i++) {
            float w = sA[i*D + lane];
            unsigned long long wp = pack2(w, w);
            a01 = fma2(pack2(sH[hbase + i], sH[hbase + 32 + i]), wp, a01);
            a23 = fma2(pack2(sH[hbase + 64 + i], sH[hbase + 96 + i]), wp, a23);
        }
        float x0, x1, x2, x3;
        unpack2(a01, x0, x1); unpack2(a23, x2, x3);
        if (r0 + 0 < N_NET) out[OUT_NET_OFF + (r0+0)*D + lane] = x0;
        if (r0 + 1 < N_NET) out[OUT_NET_OFF + (r0+1)*D + lane] = x1;
        if (r0 + 2 < N_NET) out[OUT_NET_OFF + (r0+2)*D + lane] = x2;
        if (r0 + 3 < N_NET) out[OUT_NET_OFF + (r0+3)*D + lane] = x3;
        return;
    }
    b -= B_NET;

    if (b < B_NODE) {
        for (int i = threadIdx.x; i < D*D; i += 256) { sA[i] = W_pins[i]; sB[i] = W_pt[i]; }
        __syncthreads();
        int r0 = b * 32 + wid * 4;
#pragma unroll
        for (int r = 0; r < 4; r++) {
            int row = r0 + r;
            sH[hbase + r*32 + lane] = (row < N_CELL) ? node_feat[row*D + lane] : 0.f;
        }
        __syncwarp();
        unsigned long long p01 = 0ull, p23 = 0ull, q01 = 0ull, q23 = 0ull;
#pragma unroll
        for (int i = 0; i < D; i++) {
            unsigned long long h01 = pack2(sH[hbase + i], sH[hbase + 32 + i]);
            unsigned long long h23 = pack2(sH[hbase + 64 + i], sH[hbase + 96 + i]);
            float wa = sA[i*D + lane];
            unsigned long long wap = pack2(wa, wa);
            float wb = sB[i*D + lane];
            unsigned long long wbp = pack2(wb, wb);
            p01 = fma2(h01, wap, p01); p23 = fma2(h23, wap, p23);
            q01 = fma2(h01, wbp, q01); q23 = fma2(h23, wbp, q23);
        }
        float x0, x1, x2, x3, y0, y1, y2, y3;
        unpack2(p01, x0, x1); unpack2(p23, x2, x3);
        unpack2(q01, y0, y1); unpack2(q23, y2, y3);
        if (r0 + 0 < N_CELL) { g_feat_pins[(r0+0)*D + lane] = __float2half_rn(x0);
                               g_feat_pt[(r0+0)*D + lane]   = __float2half_rn(y0); }
        if (r0 + 1 < N_CELL) { g_feat_pins[(r0+1)*D + lane] = __float2half_rn(x1);
                               g_feat_pt[(r0+1)*D + lane]   = __float2half_rn(y1); }
        if (r0 + 2 < N_CELL) { g_feat_pins[(r0+2)*D + lane] = __float2half_rn(x2);
                               g_feat_pt[(r0+2)*D + lane]   = __float2half_rn(y2); }
        if (r0 + 3 < N_CELL) { g_feat_pins[(r0+3)*D + lane] = __float2half_rn(x3);
                               g_feat_pt[(r0+3)*D + lane]   = __float2half_rn(y3); }
        return;
    }
    b -= B_NODE;

    // ---- gcell feats: g_feat_conn = hanna@W_connect (fp16) ----
    for (int i = threadIdx.x; i < D*D; i += 256) sA[i] = W_connect[i];
    __syncthreads();
    int r0 = b * 32 + wid * 4;
#pragma unroll
    for (int r = 0; r < 4; r++) {
        int row = r0 + r;
        sH[hbase + r*32 + lane] = (row < N_GCELL) ? hanna_feat[row*D + lane] : 0.f;
    }
    __syncwarp();
    unsigned long long a01 = 0ull, a23 = 0ull;
#pragma unroll
    for (int i = 0; i < D; i++) {
        float w = sA[i*D + lane];
        unsigned long long wp = pack2(w, w);
        a01 = fma2(pack2(sH[hbase + i], sH[hbase + 32 + i]), wp, a01);
        a23 = fma2(pack2(sH[hbase + 64 + i], sH[hbase + 96 + i]), wp, a23);
    }
    float x0, x1, x2, x3;
    unpack2(a01, x0, x1); unpack2(a23, x2, x3);
    g_feat_conn[(r0+0)*D + lane] = __float2half_rn(x0);
    g_feat_conn[(r0+1)*D + lane] = __float2half_rn(x1);
    g_feat_conn[(r0+2)*D + lane] = __float2half_rn(x2);
    g_feat_conn[(r0+3)*D + lane] = __float2half_rn(x3);
}

// ------------- m2: per-node NNConv matrices + trailing scale region -------------
// M_n[p,o] = sum_i h_n[i]*W_topo[p, i*D+o];   c_n[o] = sum_i h_n[i]*b_topo[i*D+o]
#define MR 4
#define M2B 938                                  // ceil(7500 groups / 8 warps)
#define SCALE_B 1055                             // ceil(CNT_TOTAL/256)
__global__ void m2_kernel(const float* __restrict__ net_feat, const float* __restrict__ hanna_feat,
                          const float* __restrict__ W_topo, const float* __restrict__ b_topo) {
    // ---- trailing region: counts -> scales, then reset counts ----
    if (blockIdx.x >= M2B) {
        int i = (blockIdx.x - M2B) * 256 + threadIdx.x;
        if (i < CNT_TOTAL) {
            float c = (float)max(g_cnt[i], 1);
            bool is_nn = (i >= CNT_PINNED_DST && i < CNT_CONN_SRC) || (i >= CNT_PF_DST);
            g_scale[i] = is_nn ? __frcp_rn(c) : rsqrtf(c);
            g_cnt[i] = 0;    // leave zeroed for the next kernel_launch invocation
        }
        return;
    }

    extern __shared__ float s[];
    float* sW2 = s;                 // WT_SIZE = 18432 floats
    float* sb  = s + WT_SIZE;       // 1024
    float* sH  = s + WT_SIZE + D*D; // 8 warps * MR * 32 = 1024
    for (int t = threadIdx.x; t < DP*D*D; t += blockDim.x) {
        int p = t >> 10;
        int rem = t & 1023;
        int i = rem >> 5;
        int o = rem & 31;
        sW2[i*(D*WT_PAD) + o*WT_PAD + p] = W_topo[t];
    }
    for (int i = threadIdx.x; i < D*D; i += blockDim.x) sb[i] = b_topo[i];
    __syncthreads();

    int wid = threadIdx.x >> 5, lane = threadIdx.x & 31;
    int g = blockIdx.x * 8 + wid;
    const int NGROUPS = (N_NET + N_GCELL) / MR;  // 7500
    if (g >= NGROUPS) return;
    int r0 = g * MR;
    int hbase = wid * (MR*32);

    unsigned int* Mout[MR];
    float* cout[MR];
#pragma unroll
    for (int r = 0; r < MR; r++) {
        int row = r0 + r;
        float hv;
        if (row < N_NET) {
            hv = net_feat[row*D + lane];
            Mout[r] = reinterpret_cast<unsigned int*>(g_Mnet_h + (size_t)row * (DP*D));
            cout[r] = g_cnet + (size_t)row * D;
        } else {
            int rr = row - N_NET;
            hv = hanna_feat[rr*D + lane];
            Mout[r] = reinterpret_cast<unsigned int*>(g_Mhan_h + (size_t)rr * (DP*D));
            cout[r] = g_chan + (size_t)rr * D;
        }
        sH[hbase + r*32 + lane] = hv;
    }
    __syncwarp();

    unsigned long long acc[MR][DP/2];
    float cacc[MR];
#pragma unroll
    for (int r = 0; r < MR; r++) {
        cacc[r] = 0.f;
#pragma unroll
        for (int pp = 0; pp < DP/2; pp++) acc[r][pp] = 0ull;
    }

#pragma unroll
    for (int i = 0; i < D; i++) {
        unsigned long long hp[MR];
        float bv = sb[i*D + lane];
#pragma unroll
        for (int r = 0; r < MR; r++) {
            float hv = sH[hbase + r*32 + i];
            hp[r] = pack2(hv, hv);
            cacc[r] += hv * bv;
        }
        const unsigned long long* wrow =
            reinterpret_cast<const unsigned long long*>(sW2 + i*(D*WT_PAD) + lane*WT_PAD);
#pragma unroll
        for (int pp = 0; pp < DP/2; pp++) {
            unsigned long long wv = wrow[pp];
#pragma unroll
            for (int r = 0; r < MR; r++) acc[r][pp] = fma2(hp[r], wv, acc[r][pp]);
        }
    }

#pragma unroll
    for (int r = 0; r < MR; r++) {
#pragma unroll
        for (int pp = 0; pp < DP/2; pp++) {
            float x, y;
            unpack2(acc[r][pp], x, y);
            __half2 h2 = __floats2half2_rn(x, y);
            Mout[r][pp*32 + lane] = *reinterpret_cast<unsigned int*>(&h2);
        }
        cout[r][lane] = cacc[r];
    }
}

// ------------- fused edge scatter: 5 regions, one edge-graph per thread ---------
// r=0 pins, r=1 connect, r=2 pt (GraphConv, fp16 feats); r=3 pinned, r=4 pf (NNConv)
#define B_EDGE 3125                                     // NE*8/256

__global__ void __launch_bounds__(256)
edge_kernel(const int* __restrict__ pins_src, const int* __restrict__ pins_dst,
            const int* __restrict__ conn_src, const int* __restrict__ conn_dst,
            const int* __restrict__ pt_src, const int* __restrict__ pt_dst,
            const float* __restrict__ pin_feat,
            const int* __restrict__ pinned_src, const int* __restrict__ pinned_dst,
            const float* __restrict__ edge_feat,
            const int* __restrict__ pf_src, const int* __restrict__ pf_dst,
            float* __restrict__ out) {
    int r = blockIdx.x / B_EDGE;
    int t = (blockIdx.x - r * B_EDGE) * 256 + threadIdx.x;
    int e = t >> 3, j = t & 7;

    if (r < 3) {
        const int* srcA; const int* dstA; const __half* feat;
        int so, do_; float* ob;
        if (r == 0)      { srcA = pins_src; dstA = pins_dst; feat = g_feat_pins;
                           so = CNT_PINS_SRC; do_ = CNT_PINS_DST; ob = out + OUT_NET_OFF; }
        else if (r == 1) { srcA = conn_src; dstA = conn_dst; feat = g_feat_conn;
                           so = CNT_CONN_SRC; do_ = CNT_CONN_DST; ob = out + OUT_GCELL_OFF; }
        else             { srcA = pt_src; dstA = pt_dst; feat = g_feat_pt;
                           so = CNT_PT_SRC; do_ = CNT_PT_DST; ob = out + OUT_GCELL_OFF; }
        int sI = srcA[e], dI = dstA[e];
        float w = g_scale[so + sI] * g_scale[do_ + dI];
        // 4 halves (8B) at o = 4j..4j+3
        float2 raw = *reinterpret_cast<const float2*>(feat + (size_t)sI*D + j*4);
        const __half2* h2 = reinterpret_cast<const __half2*>(&raw);
        float2 f01 = __half22float2(h2[0]);
        float2 f23 = __half22float2(h2[1]);
        float4 v = make_float4(f01.x * w, f01.y * w, f23.x * w, f23.y * w);
        red_add_v4(ob + (size_t)dI*D + j*4, v);
        return;
    }

    // NNConv region (one graph per thread)
    int which = r - 3;
    const float* ef  = which == 0 ? pin_feat   : edge_feat;
    const int*   src = which == 0 ? pinned_src : pf_src;
    const int*   dst = which == 0 ? pinned_dst : pf_dst;
    const __half* M  = which == 0 ? g_Mnet_h   : g_Mhan_h;
    const float* c   = which == 0 ? g_cnet     : g_chan;
    const float* scl = which == 0 ? g_scale + CNT_PINNED_DST : g_scale + CNT_PF_DST;

    int sI = src[e], dI = dst[e];
    float inv = scl[dI];

    const float4* efp = reinterpret_cast<const float4*>(ef + (size_t)e * DP);
    float4 e0 = efp[0], e1 = efp[1], e2 = efp[2], e3 = efp[3];
    float efv[DP] = { e0.x, e0.y, e0.z, e0.w, e1.x, e1.y, e1.z, e1.w,
                      e2.x, e2.y, e2.z, e2.w, e3.x, e3.y, e3.z, e3.w };

    // M halves layout: pp*64 + o*2 + parity. uint4 index for (pp, lane j): pp*8 + j
    const uint4* Mp = reinterpret_cast<const uint4*>(M + (size_t)sI * (DP*D));
    float4 acc = *reinterpret_cast<const float4*>(c + (size_t)sI*D + j*4);
#pragma unroll
    for (int pp = 0; pp < DP/2; pp++) {
        uint4 v = Mp[pp*8 + j];
        float ef0 = efv[2*pp], ef1 = efv[2*pp+1];
        const __half2* h2 = reinterpret_cast<const __half2*>(&v);
        float2 f0 = __half22float2(h2[0]);
        float2 f1 = __half22float2(h2[1]);
        float2 f2 = __half22float2(h2[2]);
        float2 f3 = __half22float2(h2[3]);
        acc.x += ef0*f0.x + ef1*f0.y;
        acc.y += ef0*f1.x + ef1*f1.y;
        acc.z += ef0*f2.x + ef1*f2.y;
        acc.w += ef0*f3.x + ef1*f3.y;
    }
    acc.x *= inv; acc.y *= inv; acc.z *= inv; acc.w *= inv;
    red_add_v4(out + (size_t)dI*D + j*4, acc);
}

// =====================================================================
extern "C" void kernel_launch(void* const* d_in, const int* in_sizes, int n_in,
                              void* d_out, int out_size) {
    const float* node_feat  = (const float*)d_in[0];
    const float* net_feat   = (const float*)d_in[1];
    const float* pin_feat   = (const float*)d_in[2];
    const float* hanna_feat = (const float*)d_in[3];
    const float* edge_feat  = (const float*)d_in[4];
    const int* pins_src     = (const int*)d_in[5];
    const int* pins_dst     = (const int*)d_in[6];
    const int* pinned_src   = (const int*)d_in[7];
    const int* pinned_dst   = (const int*)d_in[8];
    const int* connect_src  = (const int*)d_in[9];
    const int* connect_dst  = (const int*)d_in[10];
    const int* pt_src       = (const int*)d_in[11];
    const int* pt_dst       = (const int*)d_in[12];
    const int* pf_src       = (const int*)d_in[13];
    const int* pf_dst       = (const int*)d_in[14];
    const float* W_net      = (const float*)d_in[15];
    const float* b_net      = (const float*)d_in[16];
    const float* W_topo     = (const float*)d_in[17];
    const float* b_topo     = (const float*)d_in[18];
    const float* W_pins     = (const float*)d_in[19];
    const float* b_pins     = (const float*)d_in[20];
    const float* W_connect  = (const float*)d_in[21];
    const float* b_connect  = (const float*)d_in[22];
    const float* W_pt       = (const float*)d_in[23];
    const float* b_pt       = (const float*)d_in[24];
    const float* b_pinned   = (const float*)d_in[25];
    const float* b_pf       = (const float*)d_in[26];
    (void)in_sizes; (void)n_in; (void)out_size;

    float* out = (float*)d_out;

    static bool s_init = false;
    static size_t m_smem = (size_t)(WT_SIZE + D*D + 8*MR*32) * sizeof(float); // 81920
    if (!s_init) {
        cudaFuncSetAttribute(m2_kernel, cudaFuncAttributeMaxDynamicSharedMemorySize, (int)m_smem);
        s_init = true;
    }

    // 1: fused prep: counting + output init + all small GEMMs (fp16 feats out)
    //    (g_cnt arrives zeroed: zero-init at load, reset by m2's scale region each run)
    prep_kernel<<<B_PREP, 256>>>(pins_src, pins_dst, pinned_dst,
                                 connect_src, connect_dst, pt_src, pt_dst, pf_dst,
                                 node_feat, net_feat, hanna_feat,
                                 W_net, b_net, W_pins, b_pins, W_connect, b_connect,
                                 W_pt, b_pt, b_pinned, b_pf, out);

    // 2: per-node NNConv matrices (fp16 p-pair-interleaved) + scale conversion region
    m2_kernel<<<M2B + SCALE_B, 256, m_smem>>>(net_feat, hanna_feat, W_topo, b_topo);

    // 3: fused edge scatters: 5 co-resident regions
    edge_kernel<<<5*B_EDGE, 256>>>(pins_src, pins_dst, connect_src, connect_dst,
                                   pt_src, pt_dst, pin_feat, pinned_src, pinned_dst,
                                   edge_feat, pf_src, pf_dst, out);
}